// round 10
// baseline (speedup 1.0000x reference)
#include <cuda_runtime.h>

#define B_    64
#define D_    512
#define N_    1200
#define K_    64
#define NT_   5            // number of 256-wide n tiles
#define NTILE 256
#define NPAD  1280         // NT_*NTILE
#define EPSF  1e-12f

// Scratch (static __device__ arrays per harness rules)
__device__ float g_a[B_ * K_ * NPAD];        // a' = softmax * invnorm(x), zero-padded in n
__device__ float g_asum_part[B_ * NT_ * K_]; // per-tile partial sums of a (unscaled)

typedef unsigned long long u64;

static __device__ __forceinline__ u64 pk(float lo, float hi){
    union { u64 u; float2 f; } t; t.f = make_float2(lo, hi); return t.u;
}
static __device__ __forceinline__ float2 upk(u64 v){
    union { u64 u; float2 f; } t; t.u = v; return t.f;
}
static __device__ __forceinline__ void fma2(u64 &acc, u64 a, u64 b){
    // packed fp32x2 FMA: acc.lo += a.lo*b.lo ; acc.hi += a.hi*b.hi
    asm("fma.rn.f32x2 %0, %1, %2, %0;" : "+l"(acc) : "l"(a), "l"(b));
}

// ---------------------------------------------------------------------------
// KA: per (batch, 256-pixel tile): logits GEMM (64k x 256n, D=512),
//     fused sumsq->invnorm, softmax over K, write a' and asum partials.
//     Thread tile 8k x 8n (4 n-pairs). W duplicated in smem, read broadcast.
//     __launch_bounds__(256, 2): cap at 128 regs so 2 CTAs/SM co-reside
//     (R7 measured 136 regs -> 1 CTA/SM, occ 12.5%, issue 31%).
// ---------------------------------------------------------------------------
__global__ __launch_bounds__(256, 2) void ka_logits(const float* __restrict__ x,
                                                    const float* __restrict__ w)
{
    __shared__ __align__(16) float SM[4096 + 2112];
    float*     xs   = SM;                                   // 16 dd x 256 floats
    u64*       ws   = reinterpret_cast<u64*>(SM + 4096);    // 16 dd x 66 dup-pairs
    const u64* xs64 = reinterpret_cast<const u64*>(SM);     // rows of 128 u64

    const int tid  = threadIdx.x;
    const int tile = blockIdx.x;
    const int b    = blockIdx.y;
    const int n0   = tile * NTILE;
    const int kg   = tid >> 5;     // warp id: k-group, 8 k per thread
    const int ng   = tid & 31;     // lane: n-pair base

    u64 acc[8][4];
    #pragma unroll
    for (int i = 0; i < 8; ++i)
        #pragma unroll
        for (int p = 0; p < 4; ++p) acc[i][p] = 0ULL;

    float4 s4 = make_float4(0.f, 0.f, 0.f, 0.f);
    const float* xb = x + (size_t)b * D_ * N_;
    const int n4  = tid & 63;      // x stager: float4 column
    const int rr  = tid >> 6;      // x stager: row group (0..3)
    const int wdd = tid & 15;      // w stager: dd
    const int wkb = tid >> 4;      // w stager: k base

    for (int c = 0; c < D_; c += 16){
        // stage x tile (16 dd x 256 n), accumulate per-pixel sumsq
        #pragma unroll
        for (int it = 0; it < 4; ++it){
            int dd = rr + 4*it;
            int nc = n0 + 4*n4;
            float4 v = make_float4(0.f, 0.f, 0.f, 0.f);
            if (nc < N_) v = *reinterpret_cast<const float4*>(xb + (size_t)(c + dd) * N_ + nc);
            *reinterpret_cast<float4*>(xs + dd*256 + 4*n4) = v;
            s4.x += v.x*v.x; s4.y += v.y*v.y; s4.z += v.z*v.z; s4.w += v.w*v.w;
        }
        // stage W duplicated: ws[dd][k] = (w,w)
        #pragma unroll
        for (int it = 0; it < 4; ++it){
            int k = wkb + 16*it;
            float wv = w[(k << 9) + c + wdd];
            ws[wdd*66 + k] = pk(wv, wv);
        }
        __syncthreads();
        #pragma unroll 4
        for (int dd = 0; dd < 16; ++dd){
            u64 xp[4];
            #pragma unroll
            for (int p = 0; p < 4; ++p) xp[p] = xs64[dd*128 + ng + 32*p];
            const ulonglong2* wr = reinterpret_cast<const ulonglong2*>(ws) + dd*33 + kg*4;
            #pragma unroll
            for (int q = 0; q < 4; ++q){
                ulonglong2 wv = wr[q];   // warp-uniform address -> broadcast LDS.128
                #pragma unroll
                for (int p = 0; p < 4; ++p){
                    fma2(acc[2*q  ][p], wv.x, xp[p]);
                    fma2(acc[2*q+1][p], wv.y, xp[p]);
                }
            }
        }
        __syncthreads();
    }

    // ---- sumsq -> invnorm (smem aliases over xs/ws regions, GEMM is done) ----
    float4* red4 = reinterpret_cast<float4*>(SM);   // 256 float4  (floats [0,1024))
    float*  sinv = SM + 1024;                       // 256 floats  [1024,1280)
    float*  red  = SM + 4096;                       // 2048 floats (ws region)

    red4[rr*64 + n4] = s4;
    __syncthreads();
    if (tid < 64){
        float4 a0 = red4[tid], a1 = red4[64+tid], a2 = red4[128+tid], a3 = red4[192+tid];
        float sx = a0.x+a1.x+a2.x+a3.x;
        float sy = a0.y+a1.y+a2.y+a3.y;
        float sz = a0.z+a1.z+a2.z+a3.z;
        float sw = a0.w+a1.w+a2.w+a3.w;
        int nb = n0 + 4*tid;
        sinv[4*tid+0] = (nb+0 < N_) ? 1.f/fmaxf(sqrtf(sx), EPSF) : 0.f;
        sinv[4*tid+1] = (nb+1 < N_) ? 1.f/fmaxf(sqrtf(sy), EPSF) : 0.f;
        sinv[4*tid+2] = (nb+2 < N_) ? 1.f/fmaxf(sqrtf(sz), EPSF) : 0.f;
        sinv[4*tid+3] = (nb+3 < N_) ? 1.f/fmaxf(sqrtf(sw), EPSF) : 0.f;
    }
    __syncthreads();

    float inv[8];
    #pragma unroll
    for (int p = 0; p < 4; ++p){
        inv[2*p]   = sinv[2*ng + 64*p];
        inv[2*p+1] = sinv[2*ng + 64*p + 1];
    }

    // scale logits by invnorm (in place in acc)
    #pragma unroll
    for (int i = 0; i < 8; ++i)
        #pragma unroll
        for (int p = 0; p < 4; ++p){
            float2 f = upk(acc[i][p]);
            acc[i][p] = pk(f.x * inv[2*p], f.y * inv[2*p+1]);
        }

    // ---- softmax over K=64 per pixel ----
    float M[8];
    #pragma unroll
    for (int p = 0; p < 4; ++p){
        float m0 = -3.4e38f, m1 = -3.4e38f;
        #pragma unroll
        for (int i = 0; i < 8; ++i){
            float2 f = upk(acc[i][p]);
            m0 = fmaxf(m0, f.x); m1 = fmaxf(m1, f.y);
        }
        red[kg*256 + 2*ng + 64*p    ] = m0;
        red[kg*256 + 2*ng + 64*p + 1] = m1;
    }
    __syncthreads();
    #pragma unroll
    for (int j = 0; j < 8; ++j){
        int nl = 2*ng + 64*(j >> 1) + (j & 1);
        float m = red[nl];
        #pragma unroll
        for (int g = 1; g < 8; ++g) m = fmaxf(m, red[g*256 + nl]);
        M[j] = m;
    }
    __syncthreads();

    float ss[8];
    #pragma unroll
    for (int j = 0; j < 8; ++j) ss[j] = 0.f;
    #pragma unroll
    for (int i = 0; i < 8; ++i)
        #pragma unroll
        for (int p = 0; p < 4; ++p){
            float2 f = upk(acc[i][p]);
            float e0 = __expf(f.x - M[2*p]);
            float e1 = __expf(f.y - M[2*p+1]);
            acc[i][p] = pk(e0, e1);
            ss[2*p] += e0; ss[2*p+1] += e1;
        }
    #pragma unroll
    for (int j = 0; j < 8; ++j)
        red[kg*256 + 2*ng + 64*(j >> 1) + (j & 1)] = ss[j];
    __syncthreads();
    float rS[8];
    #pragma unroll
    for (int j = 0; j < 8; ++j){
        int nl = 2*ng + 64*(j >> 1) + (j & 1);
        float s = red[nl];
        #pragma unroll
        for (int g = 1; g < 8; ++g) s += red[g*256 + nl];
        rS[j] = 1.f / s;
    }

    // ---- write a' = a * invnorm (0 in padding) + asum partials ----
    float as_[8];
    #pragma unroll
    for (int i = 0; i < 8; ++i) as_[i] = 0.f;
    float* ga = g_a + ((size_t)(b*K_) + kg*8) * NPAD;
    #pragma unroll
    for (int i = 0; i < 8; ++i){
        #pragma unroll
        for (int p = 0; p < 4; ++p){
            int nl = 2*ng + 64*p;
            int n  = n0 + nl;
            float2 f = upk(acc[i][p]);
            float a0 = f.x * rS[2*p];
            float a1 = f.y * rS[2*p+1];
            if (n >= N_) { a0 = 0.f; a1 = 0.f; }   // N_ even, n even -> joint validity
            as_[i] += a0 + a1;
            *reinterpret_cast<float2*>(ga + (size_t)i*NPAD + n) =
                make_float2(a0 * inv[2*p], a1 * inv[2*p+1]);
        }
    }
    #pragma unroll
    for (int i = 0; i < 8; ++i){
        float r = as_[i];
        #pragma unroll
        for (int off = 16; off; off >>= 1) r += __shfl_xor_sync(0xffffffffu, r, off);
        if (ng == 0) g_asum_part[(b*NT_ + tile)*K_ + kg*8 + i] = r;
    }
}

// ---------------------------------------------------------------------------
// KB: vlad_raw[b,k,d] = sum_n a'[b,k,n] * x[b,d,n]
//     CTA = (128-d tile, batch), 128 threads, thread tile 16k x 4d.
//     a' duplicated in smem, read broadcast; x as natural d-pairs.
//     __launch_bounds__(128, 4): 4 CTAs/SM (16 warps) for latency hiding;
//     smem 4 x 33.5 KB = 134 KB < 228 KB.
// ---------------------------------------------------------------------------
__global__ __launch_bounds__(128, 4) void kb_vlad(const float* __restrict__ x,
                                                  float* __restrict__ out)
{
    __shared__ __align__(16) float xsm[32*130];  // [nn][d], rows of 130 floats
    __shared__ __align__(16) u64   adu[32*66];   // [nn][k] duplicated pairs
    const u64* xs64 = reinterpret_cast<const u64*>(xsm);   // rows of 65 u64

    const int tid = threadIdx.x;
    const int d0  = blockIdx.x * 128;
    const int b   = blockIdx.y;
    const int kg  = tid >> 5;     // warp id: 16 k per thread
    const int dg  = tid & 31;     // lane: d-pair base
    const int sg  = tid >> 5, sl = tid & 31;   // stager mapping

    u64 acc[16][2];
    #pragma unroll
    for (int i = 0; i < 16; ++i){ acc[i][0] = 0ULL; acc[i][1] = 0ULL; }

    const float* xb = x   + (size_t)b * D_ * N_;
    const float* ab = g_a + (size_t)b * K_ * NPAD;

    for (int n0 = 0; n0 < NPAD; n0 += 32){
        #pragma unroll
        for (int it = 0; it < 16; ++it){
            int k = sg + 4*it;
            float v = ab[(size_t)k*NPAD + n0 + sl];
            adu[sl*66 + k] = pk(v, v);
        }
        #pragma unroll
        for (int it = 0; it < 32; ++it){
            int d  = sg + 4*it;
            int gn = n0 + sl;
            float v = (gn < N_) ? xb[(size_t)(d0 + d)*N_ + gn] : 0.f;
            xsm[sl*130 + d] = v;
        }
        __syncthreads();
        #pragma unroll 4
        for (int nn = 0; nn < 32; ++nn){
            u64 xp0 = xs64[nn*65 + dg];
            u64 xp1 = xs64[nn*65 + 32 + dg];
            const ulonglong2* ar = reinterpret_cast<const ulonglong2*>(adu) + nn*33 + kg*8;
            #pragma unroll
            for (int q = 0; q < 8; ++q){
                ulonglong2 av = ar[q];   // warp-uniform -> broadcast
                fma2(acc[2*q  ][0], av.x, xp0);
                fma2(acc[2*q  ][1], av.x, xp1);
                fma2(acc[2*q+1][0], av.y, xp0);
                fma2(acc[2*q+1][1], av.y, xp1);
            }
        }
        __syncthreads();
    }

    float* ob = out + ((size_t)(b*K_) + kg*16) * D_ + d0;
    #pragma unroll
    for (int i = 0; i < 16; ++i)
        #pragma unroll
        for (int p = 0; p < 2; ++p){
            float2 f = upk(acc[i][p]);
            *reinterpret_cast<float2*>(ob + (size_t)i*D_ + 2*(dg + 32*p)) = f;
        }
}

// ---------------------------------------------------------------------------
// KC: per (k,b): asum from partials, centroid residual, intra-normalize row,
//     with global L2 norm folded in: rows are unit after intra-norm, so the
//     global norm is exactly sqrt(K)=8 -> multiply by 0.125.
// ---------------------------------------------------------------------------
__global__ __launch_bounds__(128) void kc_norm(float* __restrict__ out,
                                               const float* __restrict__ cent)
{
    __shared__ float sh[128];
    const int k = blockIdx.x, b = blockIdx.y;
    const int tid = threadIdx.x;

    float s = (tid < NT_) ? g_asum_part[(b*NT_ + tid)*K_ + k] : 0.f;
    sh[tid] = s; __syncthreads();
    for (int o = 64; o; o >>= 1){ if (tid < o) sh[tid] += sh[tid + o]; __syncthreads(); }
    float asum = sh[0];
    __syncthreads();

    float*       row  = out  + ((size_t)(b*K_ + k))*D_;
    const float* crow = cent + (size_t)k*D_;
    float v[4]; float sq = 0.f;
    #pragma unroll
    for (int j = 0; j < 4; ++j){
        int d = tid + 128*j;
        v[j] = row[d] - asum * crow[d];
        sq += v[j]*v[j];
    }
    sh[tid] = sq; __syncthreads();
    for (int o = 64; o; o >>= 1){ if (tid < o) sh[tid] += sh[tid + o]; __syncthreads(); }
    float inv = 0.125f / fmaxf(sqrtf(sh[0]), EPSF);
    #pragma unroll
    for (int j = 0; j < 4; ++j) row[tid + 128*j] = v[j] * inv;
}

// ---------------------------------------------------------------------------
extern "C" void kernel_launch(void* const* d_in, const int* in_sizes, int n_in,
                              void* d_out, int out_size)
{
    const float* x = (const float*)d_in[0];   // (B, D, H, W)
    const float* w = (const float*)d_in[1];   // (K, D)
    const float* c = (const float*)d_in[2];   // (K, D)
    float* out = (float*)d_out;               // (B, K*D)

    ka_logits<<<dim3(NT_, B_), 256>>>(x, w);
    kb_vlad  <<<dim3(D_/128, B_), 128>>>(x, out);
    kc_norm  <<<dim3(K_, B_), 128>>>(out, c);
}

// round 11
// speedup vs baseline: 1.6190x; 1.6190x over previous
#include <cuda_runtime.h>

#define B_    64
#define D_    512
#define N_    1200
#define K_    64
#define NT_   5            // number of 256-wide n tiles
#define NTILE 256
#define NPAD  1280         // NT_*NTILE
#define EPSF  1e-12f

// Scratch (static __device__ arrays per harness rules)
__device__ float g_a[B_ * K_ * NPAD];        // a' = softmax * invnorm(x), zero-padded in n
__device__ float g_asum_part[B_ * NT_ * K_]; // per-tile partial sums of a (unscaled)

typedef unsigned long long u64;

static __device__ __forceinline__ u64 pk(float lo, float hi){
    union { u64 u; float2 f; } t; t.f = make_float2(lo, hi); return t.u;
}
static __device__ __forceinline__ float2 upk(u64 v){
    union { u64 u; float2 f; } t; t.u = v; return t.f;
}
static __device__ __forceinline__ void fma2(u64 &acc, u64 a, u64 b){
    // packed fp32x2 FMA: acc.lo += a.lo*b.lo ; acc.hi += a.hi*b.hi
    asm("fma.rn.f32x2 %0, %1, %2, %0;" : "+l"(acc) : "l"(a), "l"(b));
}

// ---------------------------------------------------------------------------
// KA: per (batch, 256-pixel tile): logits GEMM (64k x 256n, D=512),
//     fused sumsq->invnorm, softmax over K, write a' and asum partials.
//     512 threads, thread tile 8k x 4n -> 16 u64 accs (32 regs), 16 warps,
//     no spills (R9 lesson: never buy occupancy with spills).
//     LDG prefetch-to-register hides staging latency behind compute.
// ---------------------------------------------------------------------------
__global__ __launch_bounds__(512) void ka_logits(const float* __restrict__ x,
                                                 const float* __restrict__ w)
{
    __shared__ __align__(16) float SM[4096 + 2112];
    float*     xs   = SM;                                   // 16 dd x 256 floats
    u64*       ws   = reinterpret_cast<u64*>(SM + 4096);    // 16 dd x 66 dup-pairs
    const u64* xs64 = reinterpret_cast<const u64*>(SM);     // rows of 128 u64

    const int tid  = threadIdx.x;
    const int tile = blockIdx.x;
    const int b    = blockIdx.y;
    const int n0   = tile * NTILE;
    const int wid  = tid >> 5;
    const int ng   = tid & 31;
    const int kg   = wid & 7;      // k-group: k = kg*8 + i
    const int nh   = wid >> 3;     // n-half: columns nh*128 .. nh*128+127

    u64 acc[8][2];
    #pragma unroll
    for (int i = 0; i < 8; ++i){ acc[i][0] = 0ULL; acc[i][1] = 0ULL; }

    float4 s4 = make_float4(0.f, 0.f, 0.f, 0.f);
    const float* xb = x + (size_t)b * D_ * N_;
    const int n4  = tid & 63;      // x stager: float4 column
    const int rr  = tid >> 6;      // x stager: row group (0..7), rows rr, rr+8
    const int wdd = tid & 15;      // w stager: dd
    const int wk  = tid >> 4;      // w stager: k and k+32

    const int  nc     = n0 + 4*n4;
    const bool nvalid = (nc < N_);

    // prefetch chunk 0
    float4 px[2]; float pw[2];
    #pragma unroll
    for (int it = 0; it < 2; ++it){
        px[it] = make_float4(0.f, 0.f, 0.f, 0.f);
        if (nvalid) px[it] = *reinterpret_cast<const float4*>(xb + (size_t)(rr + 8*it) * N_ + nc);
        pw[it] = w[((wk + 32*it) << 9) + wdd];
    }

    for (int c = 0; c < D_; c += 16){
        // store staged chunk (sync at loop bottom ordered prev compute before this)
        *reinterpret_cast<float4*>(xs + rr*256      + 4*n4) = px[0];
        *reinterpret_cast<float4*>(xs + (rr+8)*256  + 4*n4) = px[1];
        s4.x += px[0].x*px[0].x + px[1].x*px[1].x;
        s4.y += px[0].y*px[0].y + px[1].y*px[1].y;
        s4.z += px[0].z*px[0].z + px[1].z*px[1].z;
        s4.w += px[0].w*px[0].w + px[1].w*px[1].w;
        ws[wdd*66 + wk     ] = pk(pw[0], pw[0]);
        ws[wdd*66 + wk + 32] = pk(pw[1], pw[1]);
        __syncthreads();

        // prefetch next chunk (independent of smem; overlaps compute below)
        if (c + 16 < D_){
            #pragma unroll
            for (int it = 0; it < 2; ++it){
                px[it] = make_float4(0.f, 0.f, 0.f, 0.f);
                if (nvalid) px[it] = *reinterpret_cast<const float4*>(
                                        xb + (size_t)(c + 16 + rr + 8*it) * N_ + nc);
                pw[it] = w[((wk + 32*it) << 9) + c + 16 + wdd];
            }
        }

        #pragma unroll
        for (int dd = 0; dd < 16; ++dd){
            u64 xp0 = xs64[dd*128 + nh*64 + ng];
            u64 xp1 = xs64[dd*128 + nh*64 + ng + 32];
            const ulonglong2* wr = reinterpret_cast<const ulonglong2*>(ws) + dd*33 + kg*4;
            #pragma unroll
            for (int q = 0; q < 4; ++q){
                ulonglong2 wv = wr[q];   // warp-uniform -> broadcast LDS.128
                fma2(acc[2*q  ][0], wv.x, xp0);
                fma2(acc[2*q  ][1], wv.x, xp1);
                fma2(acc[2*q+1][0], wv.y, xp0);
                fma2(acc[2*q+1][1], wv.y, xp1);
            }
        }
        __syncthreads();
    }

    // ---- sumsq -> invnorm ----
    float4* red4 = reinterpret_cast<float4*>(SM);   // 512 float4 = floats [0,2048)
    float*  sinv = SM + 2048;                       // 256 floats [2048,2304)
    float*  red  = SM + 4096;                       // 2048 floats (ws region)

    red4[rr*64 + n4] = s4;
    __syncthreads();
    if (tid < 64){
        float sx = 0.f, sy = 0.f, sz = 0.f, sw = 0.f;
        #pragma unroll
        for (int r = 0; r < 8; ++r){
            float4 a0 = red4[r*64 + tid];
            sx += a0.x; sy += a0.y; sz += a0.z; sw += a0.w;
        }
        int nb = n0 + 4*tid;
        sinv[4*tid+0] = (nb+0 < N_) ? 1.f/fmaxf(sqrtf(sx), EPSF) : 0.f;
        sinv[4*tid+1] = (nb+1 < N_) ? 1.f/fmaxf(sqrtf(sy), EPSF) : 0.f;
        sinv[4*tid+2] = (nb+2 < N_) ? 1.f/fmaxf(sqrtf(sz), EPSF) : 0.f;
        sinv[4*tid+3] = (nb+3 < N_) ? 1.f/fmaxf(sqrtf(sw), EPSF) : 0.f;
    }
    __syncthreads();

    const int nlb = nh*128 + 2*ng;        // nl(p,e) = nlb + 64*p + e
    float inv[4];
    #pragma unroll
    for (int p = 0; p < 2; ++p){
        inv[2*p]   = sinv[nlb + 64*p];
        inv[2*p+1] = sinv[nlb + 64*p + 1];
    }

    // scale logits by invnorm
    #pragma unroll
    for (int i = 0; i < 8; ++i)
        #pragma unroll
        for (int p = 0; p < 2; ++p){
            float2 f = upk(acc[i][p]);
            acc[i][p] = pk(f.x * inv[2*p], f.y * inv[2*p+1]);
        }

    // ---- softmax over K=64 per pixel ----
    #pragma unroll
    for (int p = 0; p < 2; ++p){
        float m0 = -3.4e38f, m1 = -3.4e38f;
        #pragma unroll
        for (int i = 0; i < 8; ++i){
            float2 f = upk(acc[i][p]);
            m0 = fmaxf(m0, f.x); m1 = fmaxf(m1, f.y);
        }
        red[kg*256 + nlb + 64*p    ] = m0;
        red[kg*256 + nlb + 64*p + 1] = m1;
    }
    __syncthreads();
    float M[4];
    #pragma unroll
    for (int j = 0; j < 4; ++j){
        int nl = nlb + 64*(j >> 1) + (j & 1);
        float m = red[nl];
        #pragma unroll
        for (int g = 1; g < 8; ++g) m = fmaxf(m, red[g*256 + nl]);
        M[j] = m;
    }
    __syncthreads();

    float ss[4] = {0.f, 0.f, 0.f, 0.f};
    #pragma unroll
    for (int i = 0; i < 8; ++i)
        #pragma unroll
        for (int p = 0; p < 2; ++p){
            float2 f = upk(acc[i][p]);
            float e0 = __expf(f.x - M[2*p]);
            float e1 = __expf(f.y - M[2*p+1]);
            acc[i][p] = pk(e0, e1);
            ss[2*p] += e0; ss[2*p+1] += e1;
        }
    #pragma unroll
    for (int j = 0; j < 4; ++j)
        red[kg*256 + nlb + 64*(j >> 1) + (j & 1)] = ss[j];
    __syncthreads();
    float rS[4];
    #pragma unroll
    for (int j = 0; j < 4; ++j){
        int nl = nlb + 64*(j >> 1) + (j & 1);
        float s = red[nl];
        #pragma unroll
        for (int g = 1; g < 8; ++g) s += red[g*256 + nl];
        rS[j] = 1.f / s;
    }

    // ---- write a' = a * invnorm (0 in padding) + asum partials ----
    float* wsum = SM;                 // 128 floats; red4/sinv no longer needed
    float* ga = g_a + ((size_t)(b*K_) + kg*8) * NPAD;
    #pragma unroll
    for (int i = 0; i < 8; ++i){
        float asi = 0.f;
        #pragma unroll
        for (int p = 0; p < 2; ++p){
            int nl = nlb + 64*p;
            int n  = n0 + nl;
            float2 f = upk(acc[i][p]);
            float a0 = f.x * rS[2*p];
            float a1 = f.y * rS[2*p+1];
            if (n >= N_) { a0 = 0.f; a1 = 0.f; }   // n even, N_ even -> joint validity
            asi += a0 + a1;
            *reinterpret_cast<float2*>(ga + (size_t)i*NPAD + n) =
                make_float2(a0 * inv[2*p], a1 * inv[2*p+1]);
        }
        #pragma unroll
        for (int off = 16; off; off >>= 1) asi += __shfl_xor_sync(0xffffffffu, asi, off);
        if (ng == 0) wsum[wid*8 + i] = asi;        // warp's 128-n half partial
    }
    __syncthreads();
    if (tid < 64)   // k = tid; halves at wsum[k] (nh=0) and wsum[64+k] (nh=1)
        g_asum_part[(b*NT_ + tile)*K_ + tid] = wsum[tid] + wsum[64 + tid];
}

// ---------------------------------------------------------------------------
// KB: vlad_raw[b,k,d] = sum_n a'[b,k,n] * x[b,d,n]
//     CTA = (128-d tile, batch), 256 threads, thread tile 8k x 4d (32-reg acc).
//     a' duplicated in smem, read broadcast; LDG prefetch-to-register.
// ---------------------------------------------------------------------------
__global__ __launch_bounds__(256) void kb_vlad(const float* __restrict__ x,
                                               float* __restrict__ out)
{
    __shared__ __align__(16) float xsm[32*130];  // [nn][d], rows of 130 floats
    __shared__ __align__(16) u64   adu[32*66];   // [nn][k] duplicated pairs
    const u64* xs64 = reinterpret_cast<const u64*>(xsm);   // rows of 65 u64

    const int tid = threadIdx.x;
    const int d0  = blockIdx.x * 128;
    const int b   = blockIdx.y;
    const int kg  = tid >> 5;     // warp id = k-group: k = kg*8 + i
    const int dg  = tid & 31;     // lane: d-pairs 2*dg and 64+2*dg
    const int sl  = tid & 31;     // stager: nn
    const int sb  = tid >> 5;     // stager: k/d base

    u64 acc[8][2];
    #pragma unroll
    for (int i = 0; i < 8; ++i){ acc[i][0] = 0ULL; acc[i][1] = 0ULL; }

    const float* xb = x   + (size_t)b * D_ * N_;
    const float* ab = g_a + (size_t)b * K_ * NPAD;

    // prefetch chunk 0
    float ra[8], rx[16];
    #pragma unroll
    for (int it = 0; it < 8; ++it)
        ra[it] = ab[(size_t)(sb + 8*it)*NPAD + sl];
    #pragma unroll
    for (int it = 0; it < 16; ++it)
        rx[it] = (sl < N_) ? xb[(size_t)(d0 + sb + 8*it)*N_ + sl] : 0.f;

    for (int n0 = 0; n0 < NPAD; n0 += 32){
        #pragma unroll
        for (int it = 0; it < 8; ++it)
            adu[sl*66 + sb + 8*it] = pk(ra[it], ra[it]);
        #pragma unroll
        for (int it = 0; it < 16; ++it)
            xsm[sl*130 + sb + 8*it] = rx[it];
        __syncthreads();

        if (n0 + 32 < NPAD){
            int gn = n0 + 32 + sl;
            #pragma unroll
            for (int it = 0; it < 8; ++it)
                ra[it] = ab[(size_t)(sb + 8*it)*NPAD + gn];
            #pragma unroll
            for (int it = 0; it < 16; ++it)
                rx[it] = (gn < N_) ? xb[(size_t)(d0 + sb + 8*it)*N_ + gn] : 0.f;
        }

        #pragma unroll 8
        for (int nn = 0; nn < 32; ++nn){
            u64 xp0 = xs64[nn*65 + dg];
            u64 xp1 = xs64[nn*65 + 32 + dg];
            const ulonglong2* ar = reinterpret_cast<const ulonglong2*>(adu) + nn*33 + kg*4;
            #pragma unroll
            for (int q = 0; q < 4; ++q){
                ulonglong2 av = ar[q];   // warp-uniform -> broadcast
                fma2(acc[2*q  ][0], av.x, xp0);
                fma2(acc[2*q  ][1], av.x, xp1);
                fma2(acc[2*q+1][0], av.y, xp0);
                fma2(acc[2*q+1][1], av.y, xp1);
            }
        }
        __syncthreads();
    }

    float* ob = out + ((size_t)(b*K_) + kg*8) * D_ + d0;
    #pragma unroll
    for (int i = 0; i < 8; ++i)
        #pragma unroll
        for (int p = 0; p < 2; ++p){
            float2 f = upk(acc[i][p]);
            *reinterpret_cast<float2*>(ob + (size_t)i*D_ + 2*dg + 64*p) = f;
        }
}

// ---------------------------------------------------------------------------
// KC: per (k,b): asum from partials, centroid residual, intra-normalize row,
//     global L2 folded in (rows unit-norm -> global norm = sqrt(64) = 8).
// ---------------------------------------------------------------------------
__global__ __launch_bounds__(128) void kc_norm(float* __restrict__ out,
                                               const float* __restrict__ cent)
{
    __shared__ float sh[128];
    const int k = blockIdx.x, b = blockIdx.y;
    const int tid = threadIdx.x;

    float s = (tid < NT_) ? g_asum_part[(b*NT_ + tid)*K_ + k] : 0.f;
    sh[tid] = s; __syncthreads();
    for (int o = 64; o; o >>= 1){ if (tid < o) sh[tid] += sh[tid + o]; __syncthreads(); }
    float asum = sh[0];
    __syncthreads();

    float*       row  = out  + ((size_t)(b*K_ + k))*D_;
    const float* crow = cent + (size_t)k*D_;
    float v[4]; float sq = 0.f;
    #pragma unroll
    for (int j = 0; j < 4; ++j){
        int d = tid + 128*j;
        v[j] = row[d] - asum * crow[d];
        sq += v[j]*v[j];
    }
    sh[tid] = sq; __syncthreads();
    for (int o = 64; o; o >>= 1){ if (tid < o) sh[tid] += sh[tid + o]; __syncthreads(); }
    float inv = 0.125f / fmaxf(sqrtf(sh[0]), EPSF);
    #pragma unroll
    for (int j = 0; j < 4; ++j) row[tid + 128*j] = v[j] * inv;
}

// ---------------------------------------------------------------------------
extern "C" void kernel_launch(void* const* d_in, const int* in_sizes, int n_in,
                              void* d_out, int out_size)
{
    const float* x = (const float*)d_in[0];   // (B, D, H, W)
    const float* w = (const float*)d_in[1];   // (K, D)
    const float* c = (const float*)d_in[2];   // (K, D)
    float* out = (float*)d_out;               // (B, K*D)

    ka_logits<<<dim3(NT_, B_), 512>>>(x, w);
    kb_vlad  <<<dim3(D_/128, B_), 256>>>(x, out);
    kc_norm  <<<dim3(K_, B_), 128>>>(out, c);
}